// round 15
// baseline (speedup 1.0000x reference)
#include <cuda_runtime.h>
#include <cuda_fp16.h>
#include <cuda_bf16.h>
#include <cstdint>

#define E_DIM 512
#define N_ROWS 16384
#define Q_ROWS 8192

// GEMM tiling: BM=128, BN=128, BK=32, 8 warps (2x4), warp tile 64x32
#define BM 128
#define BN 128
#define BK 32
#define GEMM_THREADS 256
#define NSTAGE 3
// padded smem row stride: 32 bf16 = 64B data + 16B pad = 80B (16B-aligned,
// conflict-free LDSM phases: row r starts at bank 20r mod 32).
#define ROWB 80

#define MARGIN 0.0078125f

// ===== device scratch (static globals; no runtime allocation) =====
__device__ float g_xsq[N_ROWS];
__device__ float g_wsq[Q_ROWS];
__device__ int   g_idx[N_ROWS];
__device__ __align__(16) __nv_bfloat16 g_xb[N_ROWS * E_DIM];   // 16 MB
__device__ __align__(16) __nv_bfloat16 g_wb[Q_ROWS * E_DIM];   //  8 MB
__device__ __align__(16) __half2 g_s[(size_t)N_ROWS * (Q_ROWS / 2)]; // 256 MB
__device__ __align__(16) float g_gmin[(size_t)N_ROWS * 256];   // 16 MB

// ---------------------------------------------------------------------------
// PTX helpers
// ---------------------------------------------------------------------------
__device__ __forceinline__ uint32_t smem_u32(const void* p) {
    uint32_t a;
    asm("{ .reg .u64 t; cvta.to.shared.u64 t, %1; cvt.u32.u64 %0, t; }"
        : "=r"(a) : "l"(p));
    return a;
}
__device__ __forceinline__ void cp_async16(uint32_t dst, const void* src) {
    asm volatile("cp.async.ca.shared.global [%0], [%1], 16;"
                 :: "r"(dst), "l"(src) : "memory");
}
__device__ __forceinline__ void cp_commit() {
    asm volatile("cp.async.commit_group;" ::: "memory");
}
template <int N>
__device__ __forceinline__ void cp_wait() {
    asm volatile("cp.async.wait_group %0;" :: "n"(N) : "memory");
}
__device__ __forceinline__ void ldm_x4(uint32_t& r0, uint32_t& r1,
                                       uint32_t& r2, uint32_t& r3, uint32_t a) {
    asm volatile("ldmatrix.sync.aligned.m8n8.x4.shared.b16 {%0,%1,%2,%3}, [%4];"
                 : "=r"(r0), "=r"(r1), "=r"(r2), "=r"(r3) : "r"(a));
}
__device__ __forceinline__ void mma_bf16(float* d, const uint32_t* a,
                                         const uint32_t* b) {
    asm volatile(
        "mma.sync.aligned.m16n8k16.row.col.f32.bf16.bf16.f32 "
        "{%0,%1,%2,%3}, {%4,%5,%6,%7}, {%8,%9}, {%0,%1,%2,%3};"
        : "+f"(d[0]), "+f"(d[1]), "+f"(d[2]), "+f"(d[3])
        : "r"(a[0]), "r"(a[1]), "r"(a[2]), "r"(a[3]), "r"(b[0]), "r"(b[1]));
}

// ---------------------------------------------------------------------------
// Kernel 1: fused prep — row sum-of-squares AND fp32->bf16 conversion in one
// pass. One block (128 threads) per row.
// ---------------------------------------------------------------------------
__global__ void prep_kernel(const float* __restrict__ x,
                            const float* __restrict__ w, int N) {
    int row = blockIdx.x;
    const float* src;
    __nv_bfloat16* dstb;
    float* dsq;
    if (row < N) {
        src = x + (size_t)row * E_DIM;
        dstb = g_xb + (size_t)row * E_DIM;
        dsq = &g_xsq[row];
    } else {
        src = w + (size_t)(row - N) * E_DIM;
        dstb = g_wb + (size_t)(row - N) * E_DIM;
        dsq = &g_wsq[row - N];
    }
    int t = threadIdx.x;  // 128 threads x 4 floats = 512
    float4 v = reinterpret_cast<const float4*>(src)[t];
    __nv_bfloat162 p0 = __floats2bfloat162_rn(v.x, v.y);
    __nv_bfloat162 p1 = __floats2bfloat162_rn(v.z, v.w);
    reinterpret_cast<uint2*>(dstb)[t] =
        make_uint2(*(uint32_t*)&p0, *(uint32_t*)&p1);
    float s = (v.x * v.x + v.y * v.y) + (v.z * v.z + v.w * v.w);
    #pragma unroll
    for (int o = 16; o > 0; o >>= 1) s += __shfl_xor_sync(0xffffffffu, s, o);
    __shared__ float ws[4];
    if ((t & 31) == 0) ws[t >> 5] = s;
    __syncthreads();
    if (t == 0) *dsq = (ws[0] + ws[1]) + (ws[2] + ws[3]);
}

// ---------------------------------------------------------------------------
// Kernel 2: bf16 screening GEMM via mma.sync (HMMA pipe), 3-stage cp.async.
// s[n,q] = w_sq[q] - 2*dot_bf16(x[n],w[q]) -> g_s (fp16).
// Per-(row, 32-col group) fp32 min -> g_gmin[row][256].
// ---------------------------------------------------------------------------
__global__ void __launch_bounds__(GEMM_THREADS, 1)
screen_gemm_kernel() {
    __shared__ __align__(16) char smA[NSTAGE][BM * ROWB];
    __shared__ __align__(16) char smB[NSTAGE][BN * ROWB];

    const int tid = threadIdx.x;
    const int lane = tid & 31;
    const int wid = tid >> 5;
    const int warpM = wid >> 2;          // 0..1
    const int warpN = wid & 3;           // 0..3
    const int mBase = blockIdx.y * BM;
    const int nBase = blockIdx.x * BN;

    uint32_t sA[NSTAGE], sB[NSTAGE];
    #pragma unroll
    for (int s = 0; s < NSTAGE; ++s) {
        sA[s] = smem_u32(smA[s]);
        sB[s] = smem_u32(smB[s]);
    }

    // loader: 512 16B chunks each for A and B; 2+2 per thread.
    auto load_stage = [&](int kt, int buf) {
        const int koff = kt * BK;
        #pragma unroll
        for (int h = 0; h < 2; ++h) {
            int c = 2 * tid + h;
            int row = c >> 2, kc = c & 3;
            cp_async16(sA[buf] + row * ROWB + kc * 16,
                       (const char*)g_xb +
                       ((size_t)(mBase + row) * E_DIM + koff + kc * 8) * 2);
            cp_async16(sB[buf] + row * ROWB + kc * 16,
                       (const char*)g_wb +
                       ((size_t)(nBase + row) * E_DIM + koff + kc * 8) * 2);
        }
        cp_commit();
    };

    float acc[4][4][4];
    #pragma unroll
    for (int i = 0; i < 4; ++i)
        #pragma unroll
        for (int j = 0; j < 4; ++j)
            #pragma unroll
            for (int k = 0; k < 4; ++k) acc[i][j][k] = 0.f;

    load_stage(0, 0);
    load_stage(1, 1);

    const int NKT = E_DIM / BK;   // 16
    for (int kt = 0; kt < NKT; ++kt) {
        if (kt + 1 < NKT) cp_wait<1>();
        else              cp_wait<0>();
        __syncthreads();   // stage kt ready; all reads of stage kt-1 done
        if (kt + 2 < NKT) load_stage(kt + 2, (kt + 2) % NSTAGE);
        const int buf = kt % NSTAGE;

        #pragma unroll
        for (int k16 = 0; k16 < 2; ++k16) {
            uint32_t af[4][4];
            #pragma unroll
            for (int i = 0; i < 4; ++i) {
                uint32_t addr = sA[buf] +
                    (warpM * 64 + i * 16 + (lane & 15)) * ROWB +
                    (k16 * 2 + (lane >> 4)) * 16;
                ldm_x4(af[i][0], af[i][1], af[i][2], af[i][3], addr);
            }
            uint32_t bf[2][4];
            #pragma unroll
            for (int j = 0; j < 2; ++j) {
                uint32_t addr = sB[buf] +
                    (warpN * 32 + j * 16 + (lane & 7) + ((lane >> 4) << 3)) * ROWB +
                    (k16 * 2 + ((lane >> 3) & 1)) * 16;
                ldm_x4(bf[j][0], bf[j][1], bf[j][2], bf[j][3], addr);
            }
            #pragma unroll
            for (int i = 0; i < 4; ++i)
                #pragma unroll
                for (int jj = 0; jj < 4; ++jj) {
                    uint32_t bb[2] = { bf[jj >> 1][(jj & 1) * 2 + 0],
                                       bf[jj >> 1][(jj & 1) * 2 + 1] };
                    mma_bf16(acc[i][jj], af[i], bb);
                }
        }
        __syncthreads();
    }

    // epilogue: s = wsq - 2*dot (fp16 to g_s) + per-32col-group fp32 min.
    const int r = lane >> 2, cp = lane & 3;
    const int g = blockIdx.x * 4 + warpN;      // 32-col group id (0..255)
    float wsq0[4], wsq1[4];
    #pragma unroll
    for (int jj = 0; jj < 4; ++jj) {
        int q = nBase + warpN * 32 + jj * 8 + cp * 2;
        wsq0[jj] = g_wsq[q];
        wsq1[jj] = g_wsq[q + 1];
    }
    #pragma unroll
    for (int i = 0; i < 4; ++i) {
        const int ra = mBase + warpM * 64 + i * 16 + r;
        const int rb = ra + 8;
        float mra = __int_as_float(0x7f800000);
        float mrb = mra;
        #pragma unroll
        for (int jj = 0; jj < 4; ++jj) {
            const int q = nBase + warpN * 32 + jj * 8 + cp * 2;
            float s0 = fmaf(-2.0f, acc[i][jj][0], wsq0[jj]);
            float s1 = fmaf(-2.0f, acc[i][jj][1], wsq1[jj]);
            float s2 = fmaf(-2.0f, acc[i][jj][2], wsq0[jj]);
            float s3 = fmaf(-2.0f, acc[i][jj][3], wsq1[jj]);
            g_s[(size_t)ra * (Q_ROWS / 2) + (q >> 1)] = __floats2half2_rn(s0, s1);
            g_s[(size_t)rb * (Q_ROWS / 2) + (q >> 1)] = __floats2half2_rn(s2, s3);
            mra = fminf(mra, fminf(s0, s1));
            mrb = fminf(mrb, fminf(s2, s3));
        }
        // reduce across the 4 cp lanes (consecutive lanes r*4+cp)
        mra = fminf(mra, __shfl_xor_sync(0xffffffffu, mra, 1));
        mra = fminf(mra, __shfl_xor_sync(0xffffffffu, mra, 2));
        mrb = fminf(mrb, __shfl_xor_sync(0xffffffffu, mrb, 1));
        mrb = fminf(mrb, __shfl_xor_sync(0xffffffffu, mrb, 2));
        if (cp == 0) {
            g_gmin[(size_t)ra * 256 + g] = mra;
            g_gmin[(size_t)rb * 256 + g] = mrb;
        }
    }
}

// ---------------------------------------------------------------------------
// Kernel 3: per-row selection. One warp per row.
// Pass 1: min over the 256 group-mins (1KB, coalesced). Pass 2: only groups
// with gmin <= thr get their 32 fp16 s values scanned; candidates get an
// exact fp32 distance (same rounding as the reference), lowest-index ties.
// ---------------------------------------------------------------------------
__global__ void __launch_bounds__(256)
select_kernel(const float* __restrict__ X, const float* __restrict__ W) {
    const int lane = threadIdx.x & 31;
    const int row = blockIdx.x * 8 + (threadIdx.x >> 5);
    const float* gm = g_gmin + (size_t)row * 256;

    float v[8];
    float mn = __int_as_float(0x7f800000);
    #pragma unroll
    for (int j = 0; j < 8; ++j) {
        v[j] = gm[lane + 32 * j];
        mn = fminf(mn, v[j]);
    }
    #pragma unroll
    for (int o = 16; o > 0; o >>= 1)
        mn = fminf(mn, __shfl_xor_sync(0xffffffffu, mn, o));
    const float thr = mn + MARGIN;

    const float xs = g_xsq[row];
    const float4* xr = reinterpret_cast<const float4*>(X + (size_t)row * E_DIM);
    const __half* srow = reinterpret_cast<const __half*>(
        g_s + (size_t)row * (Q_ROWS / 2));
    float bestv = __int_as_float(0x7f800000);
    int bestq = 0x7fffffff;

    #pragma unroll
    for (int j = 0; j < 8; ++j) {
        unsigned gmask = __ballot_sync(0xffffffffu, v[j] <= thr);
        while (gmask) {
            int src = __ffs(gmask) - 1;
            gmask &= gmask - 1;
            const int q0 = (src + 32 * j) * 32;
            float sv = __half2float(srow[q0 + lane]);
            unsigned cmask = __ballot_sync(0xffffffffu, sv <= thr);
            while (cmask) {
                int cs = __ffs(cmask) - 1;
                cmask &= cmask - 1;
                const int q = q0 + cs;
                const float4* wr =
                    reinterpret_cast<const float4*>(W + (size_t)q * E_DIM);
                float part = 0.f;
                #pragma unroll
                for (int c = 0; c < 4; ++c) {
                    float4 a = xr[lane + 32 * c];
                    float4 b = wr[lane + 32 * c];
                    part = fmaf(a.x, b.x, part);
                    part = fmaf(a.y, b.y, part);
                    part = fmaf(a.z, b.z, part);
                    part = fmaf(a.w, b.w, part);
                }
                #pragma unroll
                for (int o = 16; o > 0; o >>= 1)
                    part += __shfl_xor_sync(0xffffffffu, part, o);
                float vv = fmaf(-2.0f, part, xs);   // matches ref rounding
                vv = vv + g_wsq[q];
                if (vv < bestv || (vv == bestv && q < bestq)) {
                    bestv = vv; bestq = q;
                }
            }
        }
    }
    if (lane == 0) g_idx[row] = bestq;
}

// ---------------------------------------------------------------------------
// Kernel 4: gather codebook rows + emit idx (unchanged).
// ---------------------------------------------------------------------------
__global__ void gather_kernel(const float* __restrict__ W,
                              float* __restrict__ out,
                              int N, long long total) {
    long long p = (long long)blockIdx.x * blockDim.x + threadIdx.x;
    if (p >= total) return;
    const long long ne = (long long)N * E_DIM;
    if (p < ne) {
        int n = (int)(p >> 9);
        int e = (int)(p & 511);
        out[p] = W[(size_t)g_idx[n] * E_DIM + e];
    } else if (p < ne + N) {
        out[p] = (float)g_idx[p - ne];
    } else {
        out[p] = 0.f;
    }
}

// ---------------------------------------------------------------------------
extern "C" void kernel_launch(void* const* d_in, const int* in_sizes, int n_in,
                              void* d_out, int out_size) {
    const float* x = (const float*)d_in[0];   // (8,2048,512) fp32
    const float* w = (const float*)d_in[1];   // (8192,512)  fp32
    const int N = in_sizes[0] / E_DIM;        // 16384
    const int Q = in_sizes[1] / E_DIM;        // 8192

    prep_kernel<<<N + Q, 128>>>(x, w, N);

    dim3 grid(Q / BN, N / BM);                // (64, 128)
    screen_gemm_kernel<<<grid, GEMM_THREADS>>>();

    select_kernel<<<N / 8, 256>>>(x, w);

    const long long total = (long long)out_size;
    const int thr = 256;
    const int blocks = (int)((total + thr - 1) / thr);
    gather_kernel<<<blocks, thr>>>(w, (float*)d_out, N, total);
}

// round 16
// speedup vs baseline: 1.0754x; 1.0754x over previous
#include <cuda_runtime.h>
#include <cuda_fp16.h>
#include <cuda_bf16.h>
#include <cstdint>

#define E_DIM 512
#define N_ROWS 16384
#define Q_ROWS 8192

// GEMM tiling: BM=128, BN=128, BK=32, 8 warps (2x4), warp tile 64x32
#define BM 128
#define BN 128
#define BK 32
#define GEMM_THREADS 256
// padded smem row stride: 32 bf16 = 64B data + 16B pad = 80B (16B-aligned,
// conflict-free LDSM phases: row r starts at bank 20r mod 32).
#define ROWB 80

#define MARGIN 0.0078125f

// ===== device scratch (static globals; no runtime allocation) =====
__device__ float g_xsq[N_ROWS];
__device__ float g_wsq[Q_ROWS];
__device__ int   g_idx[N_ROWS];
__device__ __align__(16) __nv_bfloat16 g_xb[N_ROWS * E_DIM];   // 16 MB
__device__ __align__(16) __nv_bfloat16 g_wb[Q_ROWS * E_DIM];   //  8 MB
__device__ __align__(16) float g_gmin[(size_t)N_ROWS * 256];   // 16 MB

// ---------------------------------------------------------------------------
// PTX helpers
// ---------------------------------------------------------------------------
__device__ __forceinline__ uint32_t smem_u32(const void* p) {
    uint32_t a;
    asm("{ .reg .u64 t; cvta.to.shared.u64 t, %1; cvt.u32.u64 %0, t; }"
        : "=r"(a) : "l"(p));
    return a;
}
__device__ __forceinline__ void cp_async16(uint32_t dst, const void* src) {
    asm volatile("cp.async.ca.shared.global [%0], [%1], 16;"
                 :: "r"(dst), "l"(src) : "memory");
}
__device__ __forceinline__ void cp_commit() {
    asm volatile("cp.async.commit_group;" ::: "memory");
}
template <int N>
__device__ __forceinline__ void cp_wait() {
    asm volatile("cp.async.wait_group %0;" :: "n"(N) : "memory");
}
__device__ __forceinline__ void ldm_x4(uint32_t& r0, uint32_t& r1,
                                       uint32_t& r2, uint32_t& r3, uint32_t a) {
    asm volatile("ldmatrix.sync.aligned.m8n8.x4.shared.b16 {%0,%1,%2,%3}, [%4];"
                 : "=r"(r0), "=r"(r1), "=r"(r2), "=r"(r3) : "r"(a));
}
__device__ __forceinline__ void mma_bf16(float* d, const uint32_t* a,
                                         const uint32_t* b) {
    asm volatile(
        "mma.sync.aligned.m16n8k16.row.col.f32.bf16.bf16.f32 "
        "{%0,%1,%2,%3}, {%4,%5,%6,%7}, {%8,%9}, {%0,%1,%2,%3};"
        : "+f"(d[0]), "+f"(d[1]), "+f"(d[2]), "+f"(d[3])
        : "r"(a[0]), "r"(a[1]), "r"(a[2]), "r"(a[3]), "r"(b[0]), "r"(b[1]));
}

// ---------------------------------------------------------------------------
// Kernel 1: fused prep — row sum-of-squares AND fp32->bf16 in one pass.
// One block (128 threads) per row.
// ---------------------------------------------------------------------------
__global__ void prep_kernel(const float* __restrict__ x,
                            const float* __restrict__ w, int N) {
    int row = blockIdx.x;
    const float* src;
    __nv_bfloat16* dstb;
    float* dsq;
    if (row < N) {
        src = x + (size_t)row * E_DIM;
        dstb = g_xb + (size_t)row * E_DIM;
        dsq = &g_xsq[row];
    } else {
        src = w + (size_t)(row - N) * E_DIM;
        dstb = g_wb + (size_t)(row - N) * E_DIM;
        dsq = &g_wsq[row - N];
    }
    int t = threadIdx.x;  // 128 threads x 4 floats = 512
    float4 v = reinterpret_cast<const float4*>(src)[t];
    __nv_bfloat162 p0 = __floats2bfloat162_rn(v.x, v.y);
    __nv_bfloat162 p1 = __floats2bfloat162_rn(v.z, v.w);
    reinterpret_cast<uint2*>(dstb)[t] =
        make_uint2(*(uint32_t*)&p0, *(uint32_t*)&p1);
    float s = (v.x * v.x + v.y * v.y) + (v.z * v.z + v.w * v.w);
    #pragma unroll
    for (int o = 16; o > 0; o >>= 1) s += __shfl_xor_sync(0xffffffffu, s, o);
    __shared__ float ws[4];
    if ((t & 31) == 0) ws[t >> 5] = s;
    __syncthreads();
    if (t == 0) *dsq = (ws[0] + ws[1]) + (ws[2] + ws[3]);
}

// ---------------------------------------------------------------------------
// Kernel 2: bf16 screening GEMM via mma.sync (HMMA pipe).
// Mainloop is byte-identical to the proven 948us version (2-stage, prefetch
// issued BEFORE cp_wait). Epilogue stores ONLY per-(row, 32-col group) fp32
// mins of s = wsq - 2*dot  ->  g_gmin[row][256]. No full s matrix.
// ---------------------------------------------------------------------------
__global__ void __launch_bounds__(GEMM_THREADS, 1)
screen_gemm_kernel() {
    __shared__ __align__(16) char smA[2][BM * ROWB];
    __shared__ __align__(16) char smB[2][BN * ROWB];

    const int tid = threadIdx.x;
    const int lane = tid & 31;
    const int wid = tid >> 5;
    const int warpM = wid >> 2;          // 0..1
    const int warpN = wid & 3;           // 0..3
    const int mBase = blockIdx.y * BM;
    const int nBase = blockIdx.x * BN;

    const uint32_t sA[2] = { smem_u32(smA[0]), smem_u32(smA[1]) };
    const uint32_t sB[2] = { smem_u32(smB[0]), smem_u32(smB[1]) };

    auto load_stage = [&](int kt, int buf) {
        const int koff = kt * BK;
        #pragma unroll
        for (int h = 0; h < 2; ++h) {
            int c = 2 * tid + h;
            int row = c >> 2, kc = c & 3;
            cp_async16(sA[buf] + row * ROWB + kc * 16,
                       (const char*)g_xb +
                       ((size_t)(mBase + row) * E_DIM + koff + kc * 8) * 2);
            cp_async16(sB[buf] + row * ROWB + kc * 16,
                       (const char*)g_wb +
                       ((size_t)(nBase + row) * E_DIM + koff + kc * 8) * 2);
        }
        cp_commit();
    };

    float acc[4][4][4];
    #pragma unroll
    for (int i = 0; i < 4; ++i)
        #pragma unroll
        for (int j = 0; j < 4; ++j)
            #pragma unroll
            for (int k = 0; k < 4; ++k) acc[i][j][k] = 0.f;

    load_stage(0, 0);

    const int NKT = E_DIM / BK;   // 16
    for (int kt = 0; kt < NKT; ++kt) {
        const int buf = kt & 1;
        if (kt + 1 < NKT) { load_stage(kt + 1, buf ^ 1); cp_wait<1>(); }
        else              { cp_wait<0>(); }
        __syncthreads();

        #pragma unroll
        for (int k16 = 0; k16 < 2; ++k16) {
            uint32_t af[4][4];
            #pragma unroll
            for (int i = 0; i < 4; ++i) {
                uint32_t addr = sA[buf] +
                    (warpM * 64 + i * 16 + (lane & 15)) * ROWB +
                    (k16 * 2 + (lane >> 4)) * 16;
                ldm_x4(af[i][0], af[i][1], af[i][2], af[i][3], addr);
            }
            uint32_t bf[2][4];
            #pragma unroll
            for (int j = 0; j < 2; ++j) {
                uint32_t addr = sB[buf] +
                    (warpN * 32 + j * 16 + (lane & 7) + ((lane >> 4) << 3)) * ROWB +
                    (k16 * 2 + ((lane >> 3) & 1)) * 16;
                ldm_x4(bf[j][0], bf[j][1], bf[j][2], bf[j][3], addr);
            }
            #pragma unroll
            for (int i = 0; i < 4; ++i)
                #pragma unroll
                for (int jj = 0; jj < 4; ++jj) {
                    uint32_t bb[2] = { bf[jj >> 1][(jj & 1) * 2 + 0],
                                       bf[jj >> 1][(jj & 1) * 2 + 1] };
                    mma_bf16(acc[i][jj], af[i], bb);
                }
        }
        __syncthreads();
    }

    // epilogue: per-(row, 32-col group) min of s = wsq - 2*dot. No s store.
    const int r = lane >> 2, cp = lane & 3;
    const int g = blockIdx.x * 4 + warpN;      // 32-col group id (0..255)
    float wsq0[4], wsq1[4];
    #pragma unroll
    for (int jj = 0; jj < 4; ++jj) {
        int q = nBase + warpN * 32 + jj * 8 + cp * 2;
        wsq0[jj] = g_wsq[q];
        wsq1[jj] = g_wsq[q + 1];
    }
    #pragma unroll
    for (int i = 0; i < 4; ++i) {
        const int ra = mBase + warpM * 64 + i * 16 + r;
        const int rb = ra + 8;
        float mra = __int_as_float(0x7f800000);
        float mrb = mra;
        #pragma unroll
        for (int jj = 0; jj < 4; ++jj) {
            float s0 = fmaf(-2.0f, acc[i][jj][0], wsq0[jj]);
            float s1 = fmaf(-2.0f, acc[i][jj][1], wsq1[jj]);
            float s2 = fmaf(-2.0f, acc[i][jj][2], wsq0[jj]);
            float s3 = fmaf(-2.0f, acc[i][jj][3], wsq1[jj]);
            mra = fminf(mra, fminf(s0, s1));
            mrb = fminf(mrb, fminf(s2, s3));
        }
        // reduce across the 4 cp lanes (consecutive lanes r*4+cp)
        mra = fminf(mra, __shfl_xor_sync(0xffffffffu, mra, 1));
        mra = fminf(mra, __shfl_xor_sync(0xffffffffu, mra, 2));
        mrb = fminf(mrb, __shfl_xor_sync(0xffffffffu, mrb, 1));
        mrb = fminf(mrb, __shfl_xor_sync(0xffffffffu, mrb, 2));
        if (cp == 0) {
            g_gmin[(size_t)ra * 256 + g] = mra;
            g_gmin[(size_t)rb * 256 + g] = mrb;
        }
    }
}

// ---------------------------------------------------------------------------
// Kernel 3: per-row selection. One warp per row, 8 warps/block.
// Pass 1: min over 256 group-mins (1KB, coalesced); thr = min + MARGIN.
// Pass 2: for each group with gmin <= thr, recompute ALL 32 exact fp32
// distances (one q per lane; x row staged in smem), argmin with the exact
// reference rounding (fmaf(-2,dot,xs)+wsq) and lowest-index tie rule.
// The true argmin's group-min <= its screen value <= min+2*screen_err < thr,
// so its group always passes.
// ---------------------------------------------------------------------------
__global__ void __launch_bounds__(256)
select_kernel(const float* __restrict__ X, const float* __restrict__ W) {
    __shared__ __align__(16) float xsm[8][E_DIM];
    const int lane = threadIdx.x & 31;
    const int wrp = threadIdx.x >> 5;
    const int row = blockIdx.x * 8 + wrp;

    // stage x row in smem (16 floats per lane)
    {
        const float4* xr = reinterpret_cast<const float4*>(X + (size_t)row * E_DIM);
        float4* xd = reinterpret_cast<float4*>(xsm[wrp]);
        #pragma unroll
        for (int c = 0; c < 4; ++c) xd[lane + 32 * c] = xr[lane + 32 * c];
    }
    __syncwarp();

    const float* gm = g_gmin + (size_t)row * 256;
    float v[8];
    float mn = __int_as_float(0x7f800000);
    #pragma unroll
    for (int j = 0; j < 8; ++j) {
        v[j] = gm[lane + 32 * j];
        mn = fminf(mn, v[j]);
    }
    #pragma unroll
    for (int o = 16; o > 0; o >>= 1)
        mn = fminf(mn, __shfl_xor_sync(0xffffffffu, mn, o));
    const float thr = mn + MARGIN;

    const float xs = g_xsq[row];
    float bestv = __int_as_float(0x7f800000);
    int bestq = 0x7fffffff;

    #pragma unroll
    for (int j = 0; j < 8; ++j) {
        unsigned gmask = __ballot_sync(0xffffffffu, v[j] <= thr);
        while (gmask) {
            int src = __ffs(gmask) - 1;
            gmask &= gmask - 1;
            const int q0 = (src + 32 * j) * 32;
            const int q = q0 + lane;              // one q per lane
            const float4* wr =
                reinterpret_cast<const float4*>(W + (size_t)q * E_DIM);
            const float4* xa = reinterpret_cast<const float4*>(xsm[wrp]);
            float d0 = 0.f, d1 = 0.f;
            #pragma unroll 16
            for (int c = 0; c < 128; c += 2) {
                float4 a0 = xa[c],     b0 = wr[c];
                float4 a1 = xa[c + 1], b1 = wr[c + 1];
                d0 = fmaf(a0.x, b0.x, d0); d0 = fmaf(a0.y, b0.y, d0);
                d0 = fmaf(a0.z, b0.z, d0); d0 = fmaf(a0.w, b0.w, d0);
                d1 = fmaf(a1.x, b1.x, d1); d1 = fmaf(a1.y, b1.y, d1);
                d1 = fmaf(a1.z, b1.z, d1); d1 = fmaf(a1.w, b1.w, d1);
            }
            float dot = d0 + d1;
            float vv = fmaf(-2.0f, dot, xs);      // matches ref rounding
            vv = vv + g_wsq[q];
            if (vv < bestv || (vv == bestv && q < bestq)) {
                bestv = vv; bestq = q;
            }
        }
    }
    // warp argmin reduce, lowest-index ties
    #pragma unroll
    for (int o = 16; o > 0; o >>= 1) {
        float v2 = __shfl_xor_sync(0xffffffffu, bestv, o);
        int   q2 = __shfl_xor_sync(0xffffffffu, bestq, o);
        if (v2 < bestv || (v2 == bestv && q2 < bestq)) {
            bestv = v2; bestq = q2;
        }
    }
    if (lane == 0) g_idx[row] = bestq;
}

// ---------------------------------------------------------------------------
// Kernel 4: gather codebook rows + emit idx (unchanged).
// ---------------------------------------------------------------------------
__global__ void gather_kernel(const float* __restrict__ W,
                              float* __restrict__ out,
                              int N, long long total) {
    long long p = (long long)blockIdx.x * blockDim.x + threadIdx.x;
    if (p >= total) return;
    const long long ne = (long long)N * E_DIM;
    if (p < ne) {
        int n = (int)(p >> 9);
        int e = (int)(p & 511);
        out[p] = W[(size_t)g_idx[n] * E_DIM + e];
    } else if (p < ne + N) {
        out[p] = (float)g_idx[p - ne];
    } else {
        out[p] = 0.f;
    }
}

// ---------------------------------------------------------------------------
extern "C" void kernel_launch(void* const* d_in, const int* in_sizes, int n_in,
                              void* d_out, int out_size) {
    const float* x = (const float*)d_in[0];   // (8,2048,512) fp32
    const float* w = (const float*)d_in[1];   // (8192,512)  fp32
    const int N = in_sizes[0] / E_DIM;        // 16384
    const int Q = in_sizes[1] / E_DIM;        // 8192

    prep_kernel<<<N + Q, 128>>>(x, w, N);

    dim3 grid(Q / BN, N / BM);                // (64, 128)
    screen_gemm_kernel<<<grid, GEMM_THREADS>>>();

    select_kernel<<<N / 8, 256>>>(x, w);

    const long long total = (long long)out_size;
    const int thr = 256;
    const int blocks = (int)((total + thr - 1) / thr);
    gather_kernel<<<blocks, thr>>>(w, (float*)d_out, N, total);
}

// round 17
// speedup vs baseline: 1.5933x; 1.4817x over previous
#include <cuda_runtime.h>
#include <cuda_fp16.h>
#include <cuda_bf16.h>
#include <cstdint>

#define E_DIM 512
#define N_ROWS 16384
#define Q_ROWS 8192

// GEMM tiling: BM=128, BN=128, BK=32, 8 warps (2x4), warp tile 64x32
#define BM 128
#define BN 128
#define BK 32
#define GEMM_THREADS 256
// padded smem row stride: 32 bf16 = 64B data + 16B pad = 80B (16B-aligned,
// conflict-free LDSM phases: row r starts at bank 20r mod 32).
#define ROWB 80

#define MARGIN 0.0078125f

// ===== device scratch (static globals; no runtime allocation) =====
__device__ float g_xsq[N_ROWS];
__device__ float g_wsq[Q_ROWS];
__device__ int   g_idx[N_ROWS];
__device__ __align__(16) __nv_bfloat16 g_xb[N_ROWS * E_DIM];   // 16 MB
__device__ __align__(16) __nv_bfloat16 g_wb[Q_ROWS * E_DIM];   //  8 MB
__device__ __align__(16) __half2 g_s[(size_t)N_ROWS * (Q_ROWS / 2)]; // 256 MB
__device__ __align__(16) float g_gmin[(size_t)N_ROWS * 256];   // 16 MB

// ---------------------------------------------------------------------------
// PTX helpers
// ---------------------------------------------------------------------------
__device__ __forceinline__ uint32_t smem_u32(const void* p) {
    uint32_t a;
    asm("{ .reg .u64 t; cvta.to.shared.u64 t, %1; cvt.u32.u64 %0, t; }"
        : "=r"(a) : "l"(p));
    return a;
}
__device__ __forceinline__ void cp_async16(uint32_t dst, const void* src) {
    asm volatile("cp.async.ca.shared.global [%0], [%1], 16;"
                 :: "r"(dst), "l"(src) : "memory");
}
__device__ __forceinline__ void cp_commit() {
    asm volatile("cp.async.commit_group;" ::: "memory");
}
template <int N>
__device__ __forceinline__ void cp_wait() {
    asm volatile("cp.async.wait_group %0;" :: "n"(N) : "memory");
}
__device__ __forceinline__ void ldm_x4(uint32_t& r0, uint32_t& r1,
                                       uint32_t& r2, uint32_t& r3, uint32_t a) {
    asm volatile("ldmatrix.sync.aligned.m8n8.x4.shared.b16 {%0,%1,%2,%3}, [%4];"
                 : "=r"(r0), "=r"(r1), "=r"(r2), "=r"(r3) : "r"(a));
}
__device__ __forceinline__ void mma_bf16(float* d, const uint32_t* a,
                                         const uint32_t* b) {
    asm volatile(
        "mma.sync.aligned.m16n8k16.row.col.f32.bf16.bf16.f32 "
        "{%0,%1,%2,%3}, {%4,%5,%6,%7}, {%8,%9}, {%0,%1,%2,%3};"
        : "+f"(d[0]), "+f"(d[1]), "+f"(d[2]), "+f"(d[3])
        : "r"(a[0]), "r"(a[1]), "r"(a[2]), "r"(a[3]), "r"(b[0]), "r"(b[1]));
}

// ---------------------------------------------------------------------------
// Kernel 1: fused prep — row sum-of-squares AND fp32->bf16 in one pass.
// One block (128 threads) per row.
// ---------------------------------------------------------------------------
__global__ void prep_kernel(const float* __restrict__ x,
                            const float* __restrict__ w, int N) {
    int row = blockIdx.x;
    const float* src;
    __nv_bfloat16* dstb;
    float* dsq;
    if (row < N) {
        src = x + (size_t)row * E_DIM;
        dstb = g_xb + (size_t)row * E_DIM;
        dsq = &g_xsq[row];
    } else {
        src = w + (size_t)(row - N) * E_DIM;
        dstb = g_wb + (size_t)(row - N) * E_DIM;
        dsq = &g_wsq[row - N];
    }
    int t = threadIdx.x;  // 128 threads x 4 floats = 512
    float4 v = reinterpret_cast<const float4*>(src)[t];
    __nv_bfloat162 p0 = __floats2bfloat162_rn(v.x, v.y);
    __nv_bfloat162 p1 = __floats2bfloat162_rn(v.z, v.w);
    reinterpret_cast<uint2*>(dstb)[t] =
        make_uint2(*(uint32_t*)&p0, *(uint32_t*)&p1);
    float s = (v.x * v.x + v.y * v.y) + (v.z * v.z + v.w * v.w);
    #pragma unroll
    for (int o = 16; o > 0; o >>= 1) s += __shfl_xor_sync(0xffffffffu, s, o);
    __shared__ float ws[4];
    if ((t & 31) == 0) ws[t >> 5] = s;
    __syncthreads();
    if (t == 0) *dsq = (ws[0] + ws[1]) + (ws[2] + ws[3]);
}

// ---------------------------------------------------------------------------
// Kernel 2: bf16 screening GEMM via mma.sync (HMMA pipe).
// Mainloop byte-identical to the proven 948us version (2-stage, prefetch
// issued BEFORE cp_wait). Epilogue: fp16 s = wsq - 2*dot -> g_s, PLUS
// per-(row, 32-col group) fp32 min -> g_gmin[row][256].
// ---------------------------------------------------------------------------
__global__ void __launch_bounds__(GEMM_THREADS, 1)
screen_gemm_kernel() {
    __shared__ __align__(16) char smA[2][BM * ROWB];
    __shared__ __align__(16) char smB[2][BN * ROWB];

    const int tid = threadIdx.x;
    const int lane = tid & 31;
    const int wid = tid >> 5;
    const int warpM = wid >> 2;          // 0..1
    const int warpN = wid & 3;           // 0..3
    const int mBase = blockIdx.y * BM;
    const int nBase = blockIdx.x * BN;

    const uint32_t sA[2] = { smem_u32(smA[0]), smem_u32(smA[1]) };
    const uint32_t sB[2] = { smem_u32(smB[0]), smem_u32(smB[1]) };

    auto load_stage = [&](int kt, int buf) {
        const int koff = kt * BK;
        #pragma unroll
        for (int h = 0; h < 2; ++h) {
            int c = 2 * tid + h;
            int row = c >> 2, kc = c & 3;
            cp_async16(sA[buf] + row * ROWB + kc * 16,
                       (const char*)g_xb +
                       ((size_t)(mBase + row) * E_DIM + koff + kc * 8) * 2);
            cp_async16(sB[buf] + row * ROWB + kc * 16,
                       (const char*)g_wb +
                       ((size_t)(nBase + row) * E_DIM + koff + kc * 8) * 2);
        }
        cp_commit();
    };

    float acc[4][4][4];
    #pragma unroll
    for (int i = 0; i < 4; ++i)
        #pragma unroll
        for (int j = 0; j < 4; ++j)
            #pragma unroll
            for (int k = 0; k < 4; ++k) acc[i][j][k] = 0.f;

    load_stage(0, 0);

    const int NKT = E_DIM / BK;   // 16
    for (int kt = 0; kt < NKT; ++kt) {
        const int buf = kt & 1;
        if (kt + 1 < NKT) { load_stage(kt + 1, buf ^ 1); cp_wait<1>(); }
        else              { cp_wait<0>(); }
        __syncthreads();

        #pragma unroll
        for (int k16 = 0; k16 < 2; ++k16) {
            uint32_t af[4][4];
            #pragma unroll
            for (int i = 0; i < 4; ++i) {
                uint32_t addr = sA[buf] +
                    (warpM * 64 + i * 16 + (lane & 15)) * ROWB +
                    (k16 * 2 + (lane >> 4)) * 16;
                ldm_x4(af[i][0], af[i][1], af[i][2], af[i][3], addr);
            }
            uint32_t bf[2][4];
            #pragma unroll
            for (int j = 0; j < 2; ++j) {
                uint32_t addr = sB[buf] +
                    (warpN * 32 + j * 16 + (lane & 7) + ((lane >> 4) << 3)) * ROWB +
                    (k16 * 2 + ((lane >> 3) & 1)) * 16;
                ldm_x4(bf[j][0], bf[j][1], bf[j][2], bf[j][3], addr);
            }
            #pragma unroll
            for (int i = 0; i < 4; ++i)
                #pragma unroll
                for (int jj = 0; jj < 4; ++jj) {
                    uint32_t bb[2] = { bf[jj >> 1][(jj & 1) * 2 + 0],
                                       bf[jj >> 1][(jj & 1) * 2 + 1] };
                    mma_bf16(acc[i][jj], af[i], bb);
                }
        }
        __syncthreads();
    }

    // epilogue: s (fp16) to g_s + per-32col-group fp32 min to g_gmin.
    const int r = lane >> 2, cp = lane & 3;
    const int g = blockIdx.x * 4 + warpN;      // 32-col group id (0..255)
    float wsq0[4], wsq1[4];
    #pragma unroll
    for (int jj = 0; jj < 4; ++jj) {
        int q = nBase + warpN * 32 + jj * 8 + cp * 2;
        wsq0[jj] = g_wsq[q];
        wsq1[jj] = g_wsq[q + 1];
    }
    #pragma unroll
    for (int i = 0; i < 4; ++i) {
        const int ra = mBase + warpM * 64 + i * 16 + r;
        const int rb = ra + 8;
        float mra = __int_as_float(0x7f800000);
        float mrb = mra;
        #pragma unroll
        for (int jj = 0; jj < 4; ++jj) {
            const int q = nBase + warpN * 32 + jj * 8 + cp * 2;
            float s0 = fmaf(-2.0f, acc[i][jj][0], wsq0[jj]);
            float s1 = fmaf(-2.0f, acc[i][jj][1], wsq1[jj]);
            float s2 = fmaf(-2.0f, acc[i][jj][2], wsq0[jj]);
            float s3 = fmaf(-2.0f, acc[i][jj][3], wsq1[jj]);
            g_s[(size_t)ra * (Q_ROWS / 2) + (q >> 1)] = __floats2half2_rn(s0, s1);
            g_s[(size_t)rb * (Q_ROWS / 2) + (q >> 1)] = __floats2half2_rn(s2, s3);
            mra = fminf(mra, fminf(s0, s1));
            mrb = fminf(mrb, fminf(s2, s3));
        }
        mra = fminf(mra, __shfl_xor_sync(0xffffffffu, mra, 1));
        mra = fminf(mra, __shfl_xor_sync(0xffffffffu, mra, 2));
        mrb = fminf(mrb, __shfl_xor_sync(0xffffffffu, mrb, 1));
        mrb = fminf(mrb, __shfl_xor_sync(0xffffffffu, mrb, 2));
        if (cp == 0) {
            g_gmin[(size_t)ra * 256 + g] = mra;
            g_gmin[(size_t)rb * 256 + g] = mrb;
        }
    }
}

// ---------------------------------------------------------------------------
// Kernel 3: per-row selection. One warp per row, 8 warps/block.
// Pass 1: min over 256 group-mins (1KB, coalesced); thr = min + MARGIN.
// Pass 2: for groups with gmin <= thr (expected ~1-2/row), read that group's
// 32 fp16 s values (64B) to find candidates <= thr; each candidate gets an
// exact warp-cooperative fp32 distance with the reference rounding
// (fmaf(-2,dot,xs)+wsq), lowest-index tie rule. The fp16 screen value of the
// true argmin is within screen_err << MARGIN of the minimum, so it is always
// in the candidate set.
// ---------------------------------------------------------------------------
__global__ void __launch_bounds__(256)
select_kernel(const float* __restrict__ X, const float* __restrict__ W) {
    const int lane = threadIdx.x & 31;
    const int row = blockIdx.x * 8 + (threadIdx.x >> 5);
    const float* gm = g_gmin + (size_t)row * 256;

    float v[8];
    float mn = __int_as_float(0x7f800000);
    #pragma unroll
    for (int j = 0; j < 8; ++j) {
        v[j] = gm[lane + 32 * j];
        mn = fminf(mn, v[j]);
    }
    #pragma unroll
    for (int o = 16; o > 0; o >>= 1)
        mn = fminf(mn, __shfl_xor_sync(0xffffffffu, mn, o));
    const float thr = mn + MARGIN;

    const float xs = g_xsq[row];
    const float4* xr = reinterpret_cast<const float4*>(X + (size_t)row * E_DIM);
    const __half* srow = reinterpret_cast<const __half*>(
        g_s + (size_t)row * (Q_ROWS / 2));
    float bestv = __int_as_float(0x7f800000);
    int bestq = 0x7fffffff;

    #pragma unroll
    for (int j = 0; j < 8; ++j) {
        unsigned gmask = __ballot_sync(0xffffffffu, v[j] <= thr);
        while (gmask) {
            int src = __ffs(gmask) - 1;
            gmask &= gmask - 1;
            const int q0 = (src + 32 * j) * 32;
            float sv = __half2float(srow[q0 + lane]);   // 64B coalesced
            unsigned cmask = __ballot_sync(0xffffffffu, sv <= thr);
            while (cmask) {
                int cs = __ffs(cmask) - 1;
                cmask &= cmask - 1;
                const int q = q0 + cs;
                const float4* wr =
                    reinterpret_cast<const float4*>(W + (size_t)q * E_DIM);
                float part = 0.f;
                #pragma unroll
                for (int c = 0; c < 4; ++c) {
                    float4 a = xr[lane + 32 * c];
                    float4 b = wr[lane + 32 * c];
                    part = fmaf(a.x, b.x, part);
                    part = fmaf(a.y, b.y, part);
                    part = fmaf(a.z, b.z, part);
                    part = fmaf(a.w, b.w, part);
                }
                #pragma unroll
                for (int o = 16; o > 0; o >>= 1)
                    part += __shfl_xor_sync(0xffffffffu, part, o);
                float vv = fmaf(-2.0f, part, xs);   // matches ref rounding
                vv = vv + g_wsq[q];
                if (vv < bestv || (vv == bestv && q < bestq)) {
                    bestv = vv; bestq = q;
                }
            }
        }
    }
    if (lane == 0) g_idx[row] = bestq;
}

// ---------------------------------------------------------------------------
// Kernel 4: gather codebook rows + emit idx (unchanged).
// ---------------------------------------------------------------------------
__global__ void gather_kernel(const float* __restrict__ W,
                              float* __restrict__ out,
                              int N, long long total) {
    long long p = (long long)blockIdx.x * blockDim.x + threadIdx.x;
    if (p >= total) return;
    const long long ne = (long long)N * E_DIM;
    if (p < ne) {
        int n = (int)(p >> 9);
        int e = (int)(p & 511);
        out[p] = W[(size_t)g_idx[n] * E_DIM + e];
    } else if (p < ne + N) {
        out[p] = (float)g_idx[p - ne];
    } else {
        out[p] = 0.f;
    }
}

// ---------------------------------------------------------------------------
extern "C" void kernel_launch(void* const* d_in, const int* in_sizes, int n_in,
                              void* d_out, int out_size) {
    const float* x = (const float*)d_in[0];   // (8,2048,512) fp32
    const float* w = (const float*)d_in[1];   // (8192,512)  fp32
    const int N = in_sizes[0] / E_DIM;        // 16384
    const int Q = in_sizes[1] / E_DIM;        // 8192

    prep_kernel<<<N + Q, 128>>>(x, w, N);

    dim3 grid(Q / BN, N / BM);                // (64, 128)
    screen_gemm_kernel<<<grid, GEMM_THREADS>>>();

    select_kernel<<<N / 8, 256>>>(x, w);

    const long long total = (long long)out_size;
    const int thr = 256;
    const int blocks = (int)((total + thr - 1) / thr);
    gather_kernel<<<blocks, thr>>>(w, (float*)d_out, N, total);
}